// round 15
// baseline (speedup 1.0000x reference)
#include <cuda_runtime.h>
#include <cstdint>

#define BK 16

// -------- scratch (device globals: allocation-free) --------
__device__ float g_s1[31500000];
__device__ float g_s2[22200000];
__device__ float g_s3[50400000];

// ===================== bf16 split helpers =====================
__device__ __forceinline__ void split2(float x0, float x1, uint32_t& hp, uint32_t& lp) {
    asm("cvt.rn.bf16x2.f32 %0, %1, %2;" : "=r"(hp) : "f"(x1), "f"(x0));
    float h0 = __uint_as_float(hp << 16);
    float h1 = __uint_as_float(hp & 0xFFFF0000u);
    float l0 = x0 - h0;
    float l1 = x1 - h1;
    asm("cvt.rn.bf16x2.f32 %0, %1, %2;" : "=r"(lp) : "f"(l1), "f"(l0));
}
__device__ __forceinline__ void mma_bf16(float* c, const uint32_t* a, const uint32_t* b) {
    asm volatile(
        "mma.sync.aligned.m16n8k16.row.col.f32.bf16.bf16.f32 "
        "{%0,%1,%2,%3}, {%4,%5,%6,%7}, {%8,%9}, {%0,%1,%2,%3};"
        : "+f"(c[0]), "+f"(c[1]), "+f"(c[2]), "+f"(c[3])
        : "r"(a[0]), "r"(a[1]), "r"(a[2]), "r"(a[3]), "r"(b[0]), "r"(b[1]));
}

// =====================================================================
// TC implicit-GEMM conv: 3-pass bf16, packed smem, BK=16, BN=64.
// 8 warps (4x2), warp tile 32x32. Division-free incremental A-loader.
// min 4 CTAs/SM for latency hiding.
// =====================================================================
template<int KH, bool ACC>
__global__ __launch_bounds__(256, 4)
void tc_conv(const float* __restrict__ In, const float* __restrict__ Wt,
             const float* __restrict__ bias, float* __restrict__ out,
             int B, int I, int Hin, int W, int O, int pad)
{
    constexpr int BM = 128, BN = 64;
    constexpr int KP = BK / 2;
    const int Hout = Hin + 2 * pad - KH + 1;
    const int M = B * Hout * W;
    const int K = I * KH;
    const int HinW = Hin * W;

    __shared__ uint32_t AsH[2][KP][BM + 8];
    __shared__ uint32_t AsL[2][KP][BM + 8];
    __shared__ uint32_t BsH[2][KP][BN + 8];
    __shared__ uint32_t BsL[2][KP][BN + 8];

    const int t    = threadIdx.x;
    const int m0   = blockIdx.x * BM;
    const int n0   = blockIdx.y * BN;
    const int warp = t >> 5;
    const int lane = t & 31;
    const int g    = lane >> 2;
    const int ctid = lane & 3;
    const int wm   = (warp & 3) * 32;
    const int wn   = (warp >> 2) * 32;

    const int arow  = t & (BM - 1);
    const int acol0 = (t >> 7) * 8;
    const int kp0   = acol0 >> 1;
    const int gm_l  = m0 + arow;
    const bool mvalid = gm_l < M;
    int lh = 0; size_t lbase = 0;
    if (mvalid) {
        int lw  = gm_l % W;
        int tmp = gm_l / W;
        lh = tmp % Hout;
        int lb = tmp / Hout;
        lbase = (size_t)lb * I * Hin * W + lw;
    }
    const float* Inb = In + lbase;

    // incremental A-loader master state (advances by BK per loadA call)
    int kh_c  = acol0 % KH;
    int hi_c  = lh - pad + kh_c;
    int off_c = (acol0 / KH) * HinW + hi_c * W;
    int krem  = K - acol0;

    int bnn[2], bkp[2];
    #pragma unroll
    for (int it = 0; it < 2; it++) {
        int p = t + it * 256;
        bnn[it] = p >> 3;
        bkp[it] = p & 7;
    }

    float regA[8];
    float regB[2][2];
    float acc[2][4][4];
    #pragma unroll
    for (int mf = 0; mf < 2; mf++)
        #pragma unroll
        for (int nf = 0; nf < 4; nf++)
            #pragma unroll
            for (int i = 0; i < 4; i++) acc[mf][nf][i] = 0.f;

    auto loadA = [&]() {
        int kh = kh_c, hi = hi_c, off = off_c, rem = krem;
        #pragma unroll
        for (int j = 0; j < 8; j++) {
            bool ok = mvalid && (j < rem) && ((unsigned)hi < (unsigned)Hin);
            regA[j] = ok ? Inb[off] : 0.f;
            kh++; hi++; off += W;
            if (kh == KH) { kh = 0; hi -= KH; off += (Hin - KH) * W; }
        }
        kh_c  += BK % KH;
        hi_c  += BK % KH;
        off_c += (BK / KH) * HinW + (BK % KH) * W;
        if (kh_c >= KH) { kh_c -= KH; hi_c -= KH; off_c += (Hin - KH) * W; }
        krem -= BK;
    };
    auto loadB = [&](int k0) {
        #pragma unroll
        for (int it = 0; it < 2; it++) {
            int gn = n0 + bnn[it];
            const float* wrow = Wt + (size_t)gn * K;
            bool nvalid = gn < O;
            int gk0 = k0 + 2 * bkp[it];
            regB[it][0] = (nvalid && gk0     < K) ? wrow[gk0]     : 0.f;
            regB[it][1] = (nvalid && gk0 + 1 < K) ? wrow[gk0 + 1] : 0.f;
        }
    };
    auto store = [&](int buf) {
        #pragma unroll
        for (int jp = 0; jp < 4; jp++) {
            uint32_t h, l;
            split2(regA[2 * jp], regA[2 * jp + 1], h, l);
            AsH[buf][kp0 + jp][arow] = h;
            AsL[buf][kp0 + jp][arow] = l;
        }
        #pragma unroll
        for (int it = 0; it < 2; it++) {
            uint32_t h, l;
            split2(regB[it][0], regB[it][1], h, l);
            BsH[buf][bkp[it]][bnn[it]] = h;
            BsL[buf][bkp[it]][bnn[it]] = l;
        }
    };
    auto compute = [&](int buf) {
        const int kpa = ctid;
        const int kpb = ctid + 4;
        uint32_t ah[2][4], al[2][4];
        #pragma unroll
        for (int mf = 0; mf < 2; mf++) {
            int ml = wm + mf * 16 + g;
            int mh = ml + 8;
            ah[mf][0] = AsH[buf][kpa][ml];
            ah[mf][1] = AsH[buf][kpa][mh];
            ah[mf][2] = AsH[buf][kpb][ml];
            ah[mf][3] = AsH[buf][kpb][mh];
            al[mf][0] = AsL[buf][kpa][ml];
            al[mf][1] = AsL[buf][kpa][mh];
            al[mf][2] = AsL[buf][kpb][ml];
            al[mf][3] = AsL[buf][kpb][mh];
        }
        uint32_t bh[4][2], bl[4][2];
        #pragma unroll
        for (int nf = 0; nf < 4; nf++) {
            int n = wn + nf * 8 + g;
            bh[nf][0] = BsH[buf][kpa][n];
            bh[nf][1] = BsH[buf][kpb][n];
            bl[nf][0] = BsL[buf][kpa][n];
            bl[nf][1] = BsL[buf][kpb][n];
        }
        #pragma unroll
        for (int mf = 0; mf < 2; mf++)
            #pragma unroll
            for (int nf = 0; nf < 4; nf++)
                mma_bf16(acc[mf][nf], ah[mf], bh[nf]);
        #pragma unroll
        for (int mf = 0; mf < 2; mf++)
            #pragma unroll
            for (int nf = 0; nf < 4; nf++)
                mma_bf16(acc[mf][nf], ah[mf], bl[nf]);
        #pragma unroll
        for (int mf = 0; mf < 2; mf++)
            #pragma unroll
            for (int nf = 0; nf < 4; nf++)
                mma_bf16(acc[mf][nf], al[mf], bh[nf]);
    };

    loadA(); loadB(0);
    store(0);
    __syncthreads();
    int buf = 0;
    for (int k0 = 0; k0 < K; k0 += BK) {
        bool has_next = (k0 + BK) < K;
        if (has_next) { loadA(); loadB(k0 + BK); }
        compute(buf);
        if (has_next) {
            store(buf ^ 1);
            __syncthreads();
            buf ^= 1;
        }
    }

    #pragma unroll
    for (int mf = 0; mf < 2; mf++) {
        #pragma unroll
        for (int half = 0; half < 2; half++) {
            int gm = m0 + wm + mf * 16 + g + half * 8;
            if (gm >= M) continue;
            int w   = gm % W;
            int tmp = gm / W;
            int h   = tmp % Hout;
            int b   = tmp / Hout;
            size_t obase = (((size_t)b * O) * Hout + h) * W + w;
            size_t ostride = (size_t)Hout * W;
            #pragma unroll
            for (int nf = 0; nf < 4; nf++) {
                #pragma unroll
                for (int jj = 0; jj < 2; jj++) {
                    int gn = n0 + wn + nf * 8 + 2 * ctid + jj;
                    if (gn >= O) continue;
                    float v = acc[mf][nf][half * 2 + jj] + bias[gn];
                    size_t idx = obase + (size_t)gn * ostride;
                    if (ACC) out[idx] = out[idx] + v;
                    else     out[idx] = v;
                }
            }
        }
    }
}

// =====================================================================
// TC Linear: packed bf16 3-pass, row-major out + optional ReLU.
// min 4 CTAs/SM.
// =====================================================================
template<int BN_, bool RELU>
__global__ __launch_bounds__(256, 4)
void tc_lin(const float* __restrict__ A, const float* __restrict__ Wt,
            const float* __restrict__ bias, float* __restrict__ out,
            int M, int N, int K)
{
    constexpr int BM = 128;
    constexpr int KP = BK / 2;
    constexpr int MF = (BN_ == 64) ? 2 : 1;
    constexpr int SL = BN_ * BK / 512;

    __shared__ uint32_t AsH[2][KP][BM + 8];
    __shared__ uint32_t AsL[2][KP][BM + 8];
    __shared__ uint32_t BsH[2][KP][BN_ + 8];
    __shared__ uint32_t BsL[2][KP][BN_ + 8];

    const int t    = threadIdx.x;
    const int m0   = blockIdx.x * BM;
    const int n0   = blockIdx.y * BN_;
    const int warp = t >> 5;
    const int lane = t & 31;
    const int g    = lane >> 2;
    const int ctid = lane & 3;
    const int wm   = (BN_ == 64) ? (warp & 3) * 32 : warp * 16;
    const int wn   = (BN_ == 64) ? (warp >> 2) * 32 : 0;

    const int arow  = t & (BM - 1);
    const int acol0 = (t >> 7) * 8;
    const int kp0   = acol0 >> 1;
    const int gm_l  = m0 + arow;
    const bool mvalid = gm_l < M;
    const float* Arow = A + (size_t)gm_l * K;

    int bnn[SL], bkp[SL];
    #pragma unroll
    for (int it = 0; it < SL; it++) {
        int p = t + it * 256;
        bnn[it] = p >> 3;
        bkp[it] = p & 7;
    }

    float regA[8];
    float regB[SL][2];
    float acc[MF][4][4];
    #pragma unroll
    for (int mf = 0; mf < MF; mf++)
        #pragma unroll
        for (int nf = 0; nf < 4; nf++)
            #pragma unroll
            for (int i = 0; i < 4; i++) acc[mf][nf][i] = 0.f;

    auto loadA = [&](int k0) {
        #pragma unroll
        for (int j = 0; j < 8; j++) {
            int gk = k0 + acol0 + j;
            regA[j] = (mvalid && gk < K) ? Arow[gk] : 0.f;
        }
    };
    auto loadB = [&](int k0) {
        #pragma unroll
        for (int it = 0; it < SL; it++) {
            int gn = n0 + bnn[it];
            const float* wrow = Wt + (size_t)gn * K;
            bool nvalid = gn < N;
            int gk0 = k0 + 2 * bkp[it];
            regB[it][0] = (nvalid && gk0     < K) ? wrow[gk0]     : 0.f;
            regB[it][1] = (nvalid && gk0 + 1 < K) ? wrow[gk0 + 1] : 0.f;
        }
    };
    auto store = [&](int buf) {
        #pragma unroll
        for (int jp = 0; jp < 4; jp++) {
            uint32_t h, l;
            split2(regA[2 * jp], regA[2 * jp + 1], h, l);
            AsH[buf][kp0 + jp][arow] = h;
            AsL[buf][kp0 + jp][arow] = l;
        }
        #pragma unroll
        for (int it = 0; it < SL; it++) {
            uint32_t h, l;
            split2(regB[it][0], regB[it][1], h, l);
            BsH[buf][bkp[it]][bnn[it]] = h;
            BsL[buf][bkp[it]][bnn[it]] = l;
        }
    };
    auto compute = [&](int buf) {
        const int kpa = ctid;
        const int kpb = ctid + 4;
        uint32_t ah[MF][4], al[MF][4];
        #pragma unroll
        for (int mf = 0; mf < MF; mf++) {
            int ml = wm + mf * 16 + g;
            int mh = ml + 8;
            ah[mf][0] = AsH[buf][kpa][ml];
            ah[mf][1] = AsH[buf][kpa][mh];
            ah[mf][2] = AsH[buf][kpb][ml];
            ah[mf][3] = AsH[buf][kpb][mh];
            al[mf][0] = AsL[buf][kpa][ml];
            al[mf][1] = AsL[buf][kpa][mh];
            al[mf][2] = AsL[buf][kpb][ml];
            al[mf][3] = AsL[buf][kpb][mh];
        }
        uint32_t bh[4][2], bl[4][2];
        #pragma unroll
        for (int nf = 0; nf < 4; nf++) {
            int n = wn + nf * 8 + g;
            bh[nf][0] = BsH[buf][kpa][n];
            bh[nf][1] = BsH[buf][kpb][n];
            bl[nf][0] = BsL[buf][kpa][n];
            bl[nf][1] = BsL[buf][kpb][n];
        }
        #pragma unroll
        for (int mf = 0; mf < MF; mf++)
            #pragma unroll
            for (int nf = 0; nf < 4; nf++)
                mma_bf16(acc[mf][nf], ah[mf], bh[nf]);
        #pragma unroll
        for (int mf = 0; mf < MF; mf++)
            #pragma unroll
            for (int nf = 0; nf < 4; nf++)
                mma_bf16(acc[mf][nf], ah[mf], bl[nf]);
        #pragma unroll
        for (int mf = 0; mf < MF; mf++)
            #pragma unroll
            for (int nf = 0; nf < 4; nf++)
                mma_bf16(acc[mf][nf], al[mf], bh[nf]);
    };

    loadA(0); loadB(0);
    store(0);
    __syncthreads();
    int buf = 0;
    for (int k0 = 0; k0 < K; k0 += BK) {
        bool has_next = (k0 + BK) < K;
        if (has_next) { loadA(k0 + BK); loadB(k0 + BK); }
        compute(buf);
        if (has_next) {
            store(buf ^ 1);
            __syncthreads();
            buf ^= 1;
        }
    }

    #pragma unroll
    for (int mf = 0; mf < MF; mf++) {
        #pragma unroll
        for (int half = 0; half < 2; half++) {
            int gm = m0 + wm + mf * 16 + g + half * 8;
            if (gm >= M) continue;
            #pragma unroll
            for (int nf = 0; nf < 4; nf++) {
                #pragma unroll
                for (int jj = 0; jj < 2; jj++) {
                    int gn = n0 + wn + nf * 8 + 2 * ctid + jj;
                    if (gn >= N) continue;
                    float v = acc[mf][nf][half * 2 + jj] + bias[gn];
                    if (RELU) v = fmaxf(v, 0.f);
                    out[(size_t)gm * N + gn] = v;
                }
            }
        }
    }
}

// ===================== SIMT conv (tiny layers) =====================
template<int BM_, int BN_, int KH, bool ACC>
__global__ __launch_bounds__(256, 2)
void conv_kernel(const float* __restrict__ In, const float* __restrict__ Wt,
                 const float* __restrict__ bias, float* __restrict__ out,
                 int B, int I, int Hin, int W, int O, int pad)
{
    constexpr int TM = 8, TN = 4;
    constexpr int GROUPS = 256 / BM_;
    constexpr int CPT    = BK / GROUPS;
    constexpr int LB     = BN_ * BK / 256;
    constexpr int NT     = BN_ / TN;

    const int Hout = Hin + 2 * pad - KH + 1;
    const int M = B * Hout * W;
    const int K = I * KH;

    __shared__ __align__(16) float As[2][BK][BM_];
    __shared__ __align__(16) float Bs[2][BK][BN_];

    const int t  = threadIdx.x;
    const int m0 = blockIdx.x * BM_;
    const int n0 = blockIdx.y * BN_;
    const int tx = t % NT;
    const int ty = t / NT;

    const int arow  = t % BM_;
    const int acol0 = (t / BM_) * CPT;
    const int gm_l  = m0 + arow;
    const bool mvalid = gm_l < M;
    int lh = 0; size_t lbase = 0;
    if (mvalid) {
        int lw  = gm_l % W;
        int tmp = gm_l / W;
        lh = tmp % Hout;
        int lb = tmp / Hout;
        lbase = (size_t)lb * I * Hin * W + lw;
    }

    float regA[CPT], regB[LB];
    float acc[TM][TN];
    #pragma unroll
    for (int i = 0; i < TM; i++)
        #pragma unroll
        for (int j = 0; j < TN; j++) acc[i][j] = 0.f;

    auto loadA = [&](int k0) {
        #pragma unroll
        for (int j = 0; j < CPT; j++) {
            int gk = k0 + acol0 + j;
            float v = 0.f;
            if (mvalid && gk < K) {
                int ii = gk / KH;
                int kh = gk - ii * KH;
                int hi = lh + kh - pad;
                if (hi >= 0 && hi < Hin)
                    v = In[lbase + (size_t)(ii * Hin + hi) * W];
            }
            regA[j] = v;
        }
    };
    auto loadB = [&](int k0) {
        #pragma unroll
        for (int j = 0; j < LB; j++) {
            int p  = t + j * 256;
            int kk = p & (BK - 1);
            int nn = p >> 4;
            int gn = n0 + nn, gk = k0 + kk;
            regB[j] = (gn < O && gk < K) ? Wt[(size_t)gn * K + gk] : 0.f;
        }
    };
    auto store = [&](int buf) {
        #pragma unroll
        for (int j = 0; j < CPT; j++) As[buf][acol0 + j][arow] = regA[j];
        #pragma unroll
        for (int j = 0; j < LB; j++) {
            int p = t + j * 256;
            Bs[buf][p & (BK - 1)][p >> 4] = regB[j];
        }
    };
    auto compute = [&](int buf) {
        #pragma unroll
        for (int k = 0; k < BK; k++) {
            float a[TM], b[TN];
            *(float4*)&a[0] = *(const float4*)&As[buf][k][ty * TM];
            *(float4*)&a[4] = *(const float4*)&As[buf][k][ty * TM + 4];
            *(float4*)&b[0] = *(const float4*)&Bs[buf][k][tx * TN];
            #pragma unroll
            for (int i = 0; i < TM; i++)
                #pragma unroll
                for (int j = 0; j < TN; j++)
                    acc[i][j] = fmaf(a[i], b[j], acc[i][j]);
        }
    };

    loadA(0); loadB(0);
    store(0);
    __syncthreads();
    int buf = 0;
    for (int k0 = 0; k0 < K; k0 += BK) {
        bool has_next = (k0 + BK) < K;
        if (has_next) { loadA(k0 + BK); loadB(k0 + BK); }
        compute(buf);
        if (has_next) {
            store(buf ^ 1);
            __syncthreads();
            buf ^= 1;
        }
    }

    #pragma unroll
    for (int i = 0; i < TM; i++) {
        int gm = m0 + ty * TM + i;
        if (gm >= M) continue;
        int w   = gm % W;
        int tmp = gm / W;
        int h   = tmp % Hout;
        int b   = tmp / Hout;
        #pragma unroll
        for (int j = 0; j < TN; j++) {
            int gn = n0 + tx * TN + j;
            if (gn >= O) continue;
            size_t idx = (((size_t)b * O + gn) * Hout + h) * W + w;
            float v = acc[i][j] + bias[gn];
            if (ACC) out[idx] = out[idx] + v;
            else     out[idx] = v;
        }
    }
}

// ===================== host-side dispatch =====================
static void run_lin_tc(const float* A, const float* W, const float* b,
                       float* out, int M, int N, int K, bool relu)
{
    int c32 = ((N + 31) / 32) * 32;
    int c64 = ((N + 63) / 64) * 64;
    if (c32 < c64) {
        dim3 g((M + 127) / 128, (N + 31) / 32);
        if (relu) tc_lin<32, true ><<<g, 256>>>(A, W, b, out, M, N, K);
        else      tc_lin<32, false><<<g, 256>>>(A, W, b, out, M, N, K);
    } else {
        dim3 g((M + 127) / 128, (N + 63) / 64);
        if (relu) tc_lin<64, true ><<<g, 256>>>(A, W, b, out, M, N, K);
        else      tc_lin<64, false><<<g, 256>>>(A, W, b, out, M, N, K);
    }
}

template<int KH, bool ACC>
static void run_conv_simt(const float* In, const float* W, const float* b,
                          float* out, int B, int I, int Hin, int Wd, int O, int pad)
{
    int Hout = Hin + 2 * pad - KH + 1;
    int M = B * Hout * Wd;
    int c32 = ((O + 31) / 32) * 32;
    int c64 = ((O + 63) / 64) * 64;
    if (c32 < c64) {
        dim3 g((M + 255) / 256, (O + 31) / 32);
        conv_kernel<256, 32, KH, ACC><<<g, 256>>>(In, W, b, out, B, I, Hin, Wd, O, pad);
    } else {
        dim3 g((M + 127) / 128, (O + 63) / 64);
        conv_kernel<128, 64, KH, ACC><<<g, 256>>>(In, W, b, out, B, I, Hin, Wd, O, pad);
    }
}

template<int KH, bool ACC>
static void run_conv_tc(const float* In, const float* W, const float* b,
                        float* out, int B, int I, int Hin, int Wd, int O, int pad)
{
    int Hout = Hin + 2 * pad - KH + 1;
    int M = B * Hout * Wd;
    dim3 g((M + 127) / 128, (O + 63) / 64);
    tc_conv<KH, ACC><<<g, 256>>>(In, W, b, out, B, I, Hin, Wd, O, pad);
}

extern "C" void kernel_launch(void* const* d_in, const int* in_sizes, int n_in,
                              void* d_out, int out_size)
{
    const float* x   = (const float*)d_in[0];
    const float* W0a = (const float*)d_in[1];  const float* b0a = (const float*)d_in[2];
    const float* Wl0 = (const float*)d_in[3];  const float* bl0 = (const float*)d_in[4];
    const float* W0b = (const float*)d_in[5];  const float* b0b = (const float*)d_in[6];
    const float* Wr0 = (const float*)d_in[7];  const float* br0 = (const float*)d_in[8];
    const float* W0c = (const float*)d_in[9];  const float* b0c = (const float*)d_in[10];
    const float* W1  = (const float*)d_in[11]; const float* b1  = (const float*)d_in[12];
    const float* Wl1 = (const float*)d_in[13]; const float* bl1 = (const float*)d_in[14];
    const float* W2  = (const float*)d_in[15]; const float* b2  = (const float*)d_in[16];
    const float* Wra = (const float*)d_in[17]; const float* bra = (const float*)d_in[18];
    const float* Wa  = (const float*)d_in[19]; const float* ba  = (const float*)d_in[20];
    const float* W3  = (const float*)d_in[21]; const float* b3  = (const float*)d_in[22];
    const float* Wl2 = (const float*)d_in[23]; const float* bl2 = (const float*)d_in[24];
    const float* W4  = (const float*)d_in[25]; const float* b4  = (const float*)d_in[26];
    const float* Wrb = (const float*)d_in[27]; const float* brb = (const float*)d_in[28];
    const float* Wb  = (const float*)d_in[29]; const float* bb  = (const float*)d_in[30];

    float* out = (float*)d_out;

    float *S1, *S2, *S3;
    cudaGetSymbolAddress((void**)&S1, g_s1);
    cudaGetSymbolAddress((void**)&S2, g_s2);
    cudaGetSymbolAddress((void**)&S3, g_s3);

    const int B = 1024;

    // ---------------- block 0 ----------------
    run_conv_simt<3, false>(x,  W0a, b0a, S1, B, 1, 5, 127, 5, 1);   // SIMT
    run_lin_tc(S1, Wl0, bl0, S2, B * 5 * 5, 81, 127, true);          // TC lin
    run_conv_simt<3, false>(S2, W0b, b0b, S3, B, 5, 5, 81, 25, 1);   // SIMT
    run_lin_tc(x,  Wr0, br0, S1, B * 1 * 5, 81, 127, false);         // TC lin
    run_conv_simt<1, true >(S1, W0c, b0c, S3, B, 1, 5, 81, 25, 0);   // SIMT

    // ---------------- block 1 ----------------
    run_conv_tc  <3, false>(S3, W1, b1, S1, B, 25, 5, 81, 75, 1);    // TC conv
    run_lin_tc(S1, Wl1, bl1, S2, B * 75 * 5, 41, 81, true);          // TC lin
    run_conv_tc  <3, false>(S2, W2, b2, S1, B, 75, 5, 41, 150, 1);   // TC conv
    run_lin_tc(S3, Wra, bra, S2, B * 25 * 5, 41, 81, false);         // TC lin
    run_conv_tc  <1, true >(S2, Wa, ba, S1, B, 25, 5, 41, 150, 0);   // TC conv

    // ---------------- block 2 ----------------
    run_conv_tc  <2, false>(S1, W3, b3, S3, B, 150, 5, 41, 300, 0);  // TC conv
    run_lin_tc(S3, Wl2, bl2, S2, B * 300 * 4, 18, 41, true);         // TC lin
    run_conv_tc  <2, false>(S2, W4, b4, out, B, 300, 4, 18, 512, 0); // TC conv
    run_lin_tc(S1, Wrb, brb, S3, B * 150 * 5, 18, 41, false);        // TC lin
    run_conv_tc  <3, true >(S3, Wb, bb, out, B, 150, 5, 18, 512, 0); // TC conv
}

// round 16
// speedup vs baseline: 1.1989x; 1.1989x over previous
#include <cuda_runtime.h>
#include <cstdint>

#define BK 16

// -------- scratch (device globals: allocation-free) --------
__device__ float g_s1[31500000];
__device__ float g_s2[22200000];
__device__ float g_s3[50400000];

// ===================== bf16 split helpers =====================
__device__ __forceinline__ void split2(float x0, float x1, uint32_t& hp, uint32_t& lp) {
    asm("cvt.rn.bf16x2.f32 %0, %1, %2;" : "=r"(hp) : "f"(x1), "f"(x0));
    float h0 = __uint_as_float(hp << 16);
    float h1 = __uint_as_float(hp & 0xFFFF0000u);
    float l0 = x0 - h0;
    float l1 = x1 - h1;
    asm("cvt.rn.bf16x2.f32 %0, %1, %2;" : "=r"(lp) : "f"(l1), "f"(l0));
}
__device__ __forceinline__ void mma_bf16(float* c, const uint32_t* a, const uint32_t* b) {
    asm volatile(
        "mma.sync.aligned.m16n8k16.row.col.f32.bf16.bf16.f32 "
        "{%0,%1,%2,%3}, {%4,%5,%6,%7}, {%8,%9}, {%0,%1,%2,%3};"
        : "+f"(c[0]), "+f"(c[1]), "+f"(c[2]), "+f"(c[3])
        : "r"(a[0]), "r"(a[1]), "r"(a[2]), "r"(a[3]), "r"(b[0]), "r"(b[1]));
}

// =====================================================================
// TC implicit-GEMM conv: 3-pass bf16, packed smem, BK=16, BN=64.
// 8 warps (4x2), warp tile 32x32. Division-free incremental A-loader.
// min 3 CTAs/SM (R14-proven optimum). BVEC: float2 B-loads (even K only).
// =====================================================================
template<int KH, bool ACC, bool BVEC>
__global__ __launch_bounds__(256, 3)
void tc_conv(const float* __restrict__ In, const float* __restrict__ Wt,
             const float* __restrict__ bias, float* __restrict__ out,
             int B, int I, int Hin, int W, int O, int pad)
{
    constexpr int BM = 128, BN = 64;
    constexpr int KP = BK / 2;
    const int Hout = Hin + 2 * pad - KH + 1;
    const int M = B * Hout * W;
    const int K = I * KH;
    const int HinW = Hin * W;

    __shared__ uint32_t AsH[2][KP][BM + 8];
    __shared__ uint32_t AsL[2][KP][BM + 8];
    __shared__ uint32_t BsH[2][KP][BN + 8];
    __shared__ uint32_t BsL[2][KP][BN + 8];

    const int t    = threadIdx.x;
    const int m0   = blockIdx.x * BM;
    const int n0   = blockIdx.y * BN;
    const int warp = t >> 5;
    const int lane = t & 31;
    const int g    = lane >> 2;
    const int ctid = lane & 3;
    const int wm   = (warp & 3) * 32;
    const int wn   = (warp >> 2) * 32;

    const int arow  = t & (BM - 1);
    const int acol0 = (t >> 7) * 8;
    const int kp0   = acol0 >> 1;
    const int gm_l  = m0 + arow;
    const bool mvalid = gm_l < M;
    int lh = 0; size_t lbase = 0;
    if (mvalid) {
        int lw  = gm_l % W;
        int tmp = gm_l / W;
        lh = tmp % Hout;
        int lb = tmp / Hout;
        lbase = (size_t)lb * I * Hin * W + lw;
    }
    const float* Inb = In + lbase;

    // incremental A-loader master state (advances by BK per loadA call)
    int kh_c  = acol0 % KH;
    int hi_c  = lh - pad + kh_c;
    int off_c = (acol0 / KH) * HinW + hi_c * W;
    int krem  = K - acol0;

    int bnn[2], bkp[2];
    #pragma unroll
    for (int it = 0; it < 2; it++) {
        int p = t + it * 256;
        bnn[it] = p >> 3;
        bkp[it] = p & 7;
    }

    float regA[8];
    float regB[2][2];
    float acc[2][4][4];
    #pragma unroll
    for (int mf = 0; mf < 2; mf++)
        #pragma unroll
        for (int nf = 0; nf < 4; nf++)
            #pragma unroll
            for (int i = 0; i < 4; i++) acc[mf][nf][i] = 0.f;

    auto loadA = [&]() {
        int kh = kh_c, hi = hi_c, off = off_c, rem = krem;
        #pragma unroll
        for (int j = 0; j < 8; j++) {
            bool ok = mvalid && (j < rem) && ((unsigned)hi < (unsigned)Hin);
            regA[j] = ok ? Inb[off] : 0.f;
            kh++; hi++; off += W;
            if (kh == KH) { kh = 0; hi -= KH; off += (Hin - KH) * W; }
        }
        kh_c  += BK % KH;
        hi_c  += BK % KH;
        off_c += (BK / KH) * HinW + (BK % KH) * W;
        if (kh_c >= KH) { kh_c -= KH; hi_c -= KH; off_c += (Hin - KH) * W; }
        krem -= BK;
    };
    auto loadB = [&](int k0) {
        #pragma unroll
        for (int it = 0; it < 2; it++) {
            int gn = n0 + bnn[it];
            const float* wrow = Wt + (size_t)gn * K;
            bool nvalid = gn < O;
            int gk0 = k0 + 2 * bkp[it];
            if (BVEC) {
                // K even => gn*K + gk0 is even => 8B-aligned
                if (nvalid && gk0 + 1 < K) {
                    float2 v = *reinterpret_cast<const float2*>(wrow + gk0);
                    regB[it][0] = v.x;
                    regB[it][1] = v.y;
                } else {
                    regB[it][0] = (nvalid && gk0 < K) ? wrow[gk0] : 0.f;
                    regB[it][1] = 0.f;
                }
            } else {
                regB[it][0] = (nvalid && gk0     < K) ? wrow[gk0]     : 0.f;
                regB[it][1] = (nvalid && gk0 + 1 < K) ? wrow[gk0 + 1] : 0.f;
            }
        }
    };
    auto store = [&](int buf) {
        #pragma unroll
        for (int jp = 0; jp < 4; jp++) {
            uint32_t h, l;
            split2(regA[2 * jp], regA[2 * jp + 1], h, l);
            AsH[buf][kp0 + jp][arow] = h;
            AsL[buf][kp0 + jp][arow] = l;
        }
        #pragma unroll
        for (int it = 0; it < 2; it++) {
            uint32_t h, l;
            split2(regB[it][0], regB[it][1], h, l);
            BsH[buf][bkp[it]][bnn[it]] = h;
            BsL[buf][bkp[it]][bnn[it]] = l;
        }
    };
    auto compute = [&](int buf) {
        const int kpa = ctid;
        const int kpb = ctid + 4;
        uint32_t ah[2][4], al[2][4];
        #pragma unroll
        for (int mf = 0; mf < 2; mf++) {
            int ml = wm + mf * 16 + g;
            int mh = ml + 8;
            ah[mf][0] = AsH[buf][kpa][ml];
            ah[mf][1] = AsH[buf][kpa][mh];
            ah[mf][2] = AsH[buf][kpb][ml];
            ah[mf][3] = AsH[buf][kpb][mh];
            al[mf][0] = AsL[buf][kpa][ml];
            al[mf][1] = AsL[buf][kpa][mh];
            al[mf][2] = AsL[buf][kpb][ml];
            al[mf][3] = AsL[buf][kpb][mh];
        }
        uint32_t bh[4][2], bl[4][2];
        #pragma unroll
        for (int nf = 0; nf < 4; nf++) {
            int n = wn + nf * 8 + g;
            bh[nf][0] = BsH[buf][kpa][n];
            bh[nf][1] = BsH[buf][kpb][n];
            bl[nf][0] = BsL[buf][kpa][n];
            bl[nf][1] = BsL[buf][kpb][n];
        }
        #pragma unroll
        for (int mf = 0; mf < 2; mf++)
            #pragma unroll
            for (int nf = 0; nf < 4; nf++)
                mma_bf16(acc[mf][nf], ah[mf], bh[nf]);
        #pragma unroll
        for (int mf = 0; mf < 2; mf++)
            #pragma unroll
            for (int nf = 0; nf < 4; nf++)
                mma_bf16(acc[mf][nf], ah[mf], bl[nf]);
        #pragma unroll
        for (int mf = 0; mf < 2; mf++)
            #pragma unroll
            for (int nf = 0; nf < 4; nf++)
                mma_bf16(acc[mf][nf], al[mf], bh[nf]);
    };

    loadA(); loadB(0);
    store(0);
    __syncthreads();
    int buf = 0;
    for (int k0 = 0; k0 < K; k0 += BK) {
        bool has_next = (k0 + BK) < K;
        if (has_next) { loadA(); loadB(k0 + BK); }
        compute(buf);
        if (has_next) {
            store(buf ^ 1);
            __syncthreads();
            buf ^= 1;
        }
    }

    #pragma unroll
    for (int mf = 0; mf < 2; mf++) {
        #pragma unroll
        for (int half = 0; half < 2; half++) {
            int gm = m0 + wm + mf * 16 + g + half * 8;
            if (gm >= M) continue;
            int w   = gm % W;
            int tmp = gm / W;
            int h   = tmp % Hout;
            int b   = tmp / Hout;
            size_t obase = (((size_t)b * O) * Hout + h) * W + w;
            size_t ostride = (size_t)Hout * W;
            #pragma unroll
            for (int nf = 0; nf < 4; nf++) {
                #pragma unroll
                for (int jj = 0; jj < 2; jj++) {
                    int gn = n0 + wn + nf * 8 + 2 * ctid + jj;
                    if (gn >= O) continue;
                    float v = acc[mf][nf][half * 2 + jj] + bias[gn];
                    size_t idx = obase + (size_t)gn * ostride;
                    if (ACC) out[idx] = out[idx] + v;
                    else     out[idx] = v;
                }
            }
        }
    }
}

// =====================================================================
// TC Linear: packed bf16 3-pass, row-major out + optional ReLU.
// min 3 CTAs/SM (R14-proven).
// =====================================================================
template<int BN_, bool RELU>
__global__ __launch_bounds__(256, 3)
void tc_lin(const float* __restrict__ A, const float* __restrict__ Wt,
            const float* __restrict__ bias, float* __restrict__ out,
            int M, int N, int K)
{
    constexpr int BM = 128;
    constexpr int KP = BK / 2;
    constexpr int MF = (BN_ == 64) ? 2 : 1;
    constexpr int SL = BN_ * BK / 512;

    __shared__ uint32_t AsH[2][KP][BM + 8];
    __shared__ uint32_t AsL[2][KP][BM + 8];
    __shared__ uint32_t BsH[2][KP][BN_ + 8];
    __shared__ uint32_t BsL[2][KP][BN_ + 8];

    const int t    = threadIdx.x;
    const int m0   = blockIdx.x * BM;
    const int n0   = blockIdx.y * BN_;
    const int warp = t >> 5;
    const int lane = t & 31;
    const int g    = lane >> 2;
    const int ctid = lane & 3;
    const int wm   = (BN_ == 64) ? (warp & 3) * 32 : warp * 16;
    const int wn   = (BN_ == 64) ? (warp >> 2) * 32 : 0;

    const int arow  = t & (BM - 1);
    const int acol0 = (t >> 7) * 8;
    const int kp0   = acol0 >> 1;
    const int gm_l  = m0 + arow;
    const bool mvalid = gm_l < M;
    const float* Arow = A + (size_t)gm_l * K;

    int bnn[SL], bkp[SL];
    #pragma unroll
    for (int it = 0; it < SL; it++) {
        int p = t + it * 256;
        bnn[it] = p >> 3;
        bkp[it] = p & 7;
    }

    float regA[8];
    float regB[SL][2];
    float acc[MF][4][4];
    #pragma unroll
    for (int mf = 0; mf < MF; mf++)
        #pragma unroll
        for (int nf = 0; nf < 4; nf++)
            #pragma unroll
            for (int i = 0; i < 4; i++) acc[mf][nf][i] = 0.f;

    auto loadA = [&](int k0) {
        #pragma unroll
        for (int j = 0; j < 8; j++) {
            int gk = k0 + acol0 + j;
            regA[j] = (mvalid && gk < K) ? Arow[gk] : 0.f;
        }
    };
    auto loadB = [&](int k0) {
        #pragma unroll
        for (int it = 0; it < SL; it++) {
            int gn = n0 + bnn[it];
            const float* wrow = Wt + (size_t)gn * K;
            bool nvalid = gn < N;
            int gk0 = k0 + 2 * bkp[it];
            regB[it][0] = (nvalid && gk0     < K) ? wrow[gk0]     : 0.f;
            regB[it][1] = (nvalid && gk0 + 1 < K) ? wrow[gk0 + 1] : 0.f;
        }
    };
    auto store = [&](int buf) {
        #pragma unroll
        for (int jp = 0; jp < 4; jp++) {
            uint32_t h, l;
            split2(regA[2 * jp], regA[2 * jp + 1], h, l);
            AsH[buf][kp0 + jp][arow] = h;
            AsL[buf][kp0 + jp][arow] = l;
        }
        #pragma unroll
        for (int it = 0; it < SL; it++) {
            uint32_t h, l;
            split2(regB[it][0], regB[it][1], h, l);
            BsH[buf][bkp[it]][bnn[it]] = h;
            BsL[buf][bkp[it]][bnn[it]] = l;
        }
    };
    auto compute = [&](int buf) {
        const int kpa = ctid;
        const int kpb = ctid + 4;
        uint32_t ah[MF][4], al[MF][4];
        #pragma unroll
        for (int mf = 0; mf < MF; mf++) {
            int ml = wm + mf * 16 + g;
            int mh = ml + 8;
            ah[mf][0] = AsH[buf][kpa][ml];
            ah[mf][1] = AsH[buf][kpa][mh];
            ah[mf][2] = AsH[buf][kpb][ml];
            ah[mf][3] = AsH[buf][kpb][mh];
            al[mf][0] = AsL[buf][kpa][ml];
            al[mf][1] = AsL[buf][kpa][mh];
            al[mf][2] = AsL[buf][kpb][ml];
            al[mf][3] = AsL[buf][kpb][mh];
        }
        uint32_t bh[4][2], bl[4][2];
        #pragma unroll
        for (int nf = 0; nf < 4; nf++) {
            int n = wn + nf * 8 + g;
            bh[nf][0] = BsH[buf][kpa][n];
            bh[nf][1] = BsH[buf][kpb][n];
            bl[nf][0] = BsL[buf][kpa][n];
            bl[nf][1] = BsL[buf][kpb][n];
        }
        #pragma unroll
        for (int mf = 0; mf < MF; mf++)
            #pragma unroll
            for (int nf = 0; nf < 4; nf++)
                mma_bf16(acc[mf][nf], ah[mf], bh[nf]);
        #pragma unroll
        for (int mf = 0; mf < MF; mf++)
            #pragma unroll
            for (int nf = 0; nf < 4; nf++)
                mma_bf16(acc[mf][nf], ah[mf], bl[nf]);
        #pragma unroll
        for (int mf = 0; mf < MF; mf++)
            #pragma unroll
            for (int nf = 0; nf < 4; nf++)
                mma_bf16(acc[mf][nf], al[mf], bh[nf]);
    };

    loadA(0); loadB(0);
    store(0);
    __syncthreads();
    int buf = 0;
    for (int k0 = 0; k0 < K; k0 += BK) {
        bool has_next = (k0 + BK) < K;
        if (has_next) { loadA(k0 + BK); loadB(k0 + BK); }
        compute(buf);
        if (has_next) {
            store(buf ^ 1);
            __syncthreads();
            buf ^= 1;
        }
    }

    #pragma unroll
    for (int mf = 0; mf < MF; mf++) {
        #pragma unroll
        for (int half = 0; half < 2; half++) {
            int gm = m0 + wm + mf * 16 + g + half * 8;
            if (gm >= M) continue;
            #pragma unroll
            for (int nf = 0; nf < 4; nf++) {
                #pragma unroll
                for (int jj = 0; jj < 2; jj++) {
                    int gn = n0 + wn + nf * 8 + 2 * ctid + jj;
                    if (gn >= N) continue;
                    float v = acc[mf][nf][half * 2 + jj] + bias[gn];
                    if (RELU) v = fmaxf(v, 0.f);
                    out[(size_t)gm * N + gn] = v;
                }
            }
        }
    }
}

// ===================== SIMT conv (tiny layers) =====================
template<int BM_, int BN_, int KH, bool ACC>
__global__ __launch_bounds__(256, 2)
void conv_kernel(const float* __restrict__ In, const float* __restrict__ Wt,
                 const float* __restrict__ bias, float* __restrict__ out,
                 int B, int I, int Hin, int W, int O, int pad)
{
    constexpr int TM = 8, TN = 4;
    constexpr int GROUPS = 256 / BM_;
    constexpr int CPT    = BK / GROUPS;
    constexpr int LB     = BN_ * BK / 256;
    constexpr int NT     = BN_ / TN;

    const int Hout = Hin + 2 * pad - KH + 1;
    const int M = B * Hout * W;
    const int K = I * KH;

    __shared__ __align__(16) float As[2][BK][BM_];
    __shared__ __align__(16) float Bs[2][BK][BN_];

    const int t  = threadIdx.x;
    const int m0 = blockIdx.x * BM_;
    const int n0 = blockIdx.y * BN_;
    const int tx = t % NT;
    const int ty = t / NT;

    const int arow  = t % BM_;
    const int acol0 = (t / BM_) * CPT;
    const int gm_l  = m0 + arow;
    const bool mvalid = gm_l < M;
    int lh = 0; size_t lbase = 0;
    if (mvalid) {
        int lw  = gm_l % W;
        int tmp = gm_l / W;
        lh = tmp % Hout;
        int lb = tmp / Hout;
        lbase = (size_t)lb * I * Hin * W + lw;
    }

    float regA[CPT], regB[LB];
    float acc[TM][TN];
    #pragma unroll
    for (int i = 0; i < TM; i++)
        #pragma unroll
        for (int j = 0; j < TN; j++) acc[i][j] = 0.f;

    auto loadA = [&](int k0) {
        #pragma unroll
        for (int j = 0; j < CPT; j++) {
            int gk = k0 + acol0 + j;
            float v = 0.f;
            if (mvalid && gk < K) {
                int ii = gk / KH;
                int kh = gk - ii * KH;
                int hi = lh + kh - pad;
                if (hi >= 0 && hi < Hin)
                    v = In[lbase + (size_t)(ii * Hin + hi) * W];
            }
            regA[j] = v;
        }
    };
    auto loadB = [&](int k0) {
        #pragma unroll
        for (int j = 0; j < LB; j++) {
            int p  = t + j * 256;
            int kk = p & (BK - 1);
            int nn = p >> 4;
            int gn = n0 + nn, gk = k0 + kk;
            regB[j] = (gn < O && gk < K) ? Wt[(size_t)gn * K + gk] : 0.f;
        }
    };
    auto store = [&](int buf) {
        #pragma unroll
        for (int j = 0; j < CPT; j++) As[buf][acol0 + j][arow] = regA[j];
        #pragma unroll
        for (int j = 0; j < LB; j++) {
            int p = t + j * 256;
            Bs[buf][p & (BK - 1)][p >> 4] = regB[j];
        }
    };
    auto compute = [&](int buf) {
        #pragma unroll
        for (int k = 0; k < BK; k++) {
            float a[TM], b[TN];
            *(float4*)&a[0] = *(const float4*)&As[buf][k][ty * TM];
            *(float4*)&a[4] = *(const float4*)&As[buf][k][ty * TM + 4];
            *(float4*)&b[0] = *(const float4*)&Bs[buf][k][tx * TN];
            #pragma unroll
            for (int i = 0; i < TM; i++)
                #pragma unroll
                for (int j = 0; j < TN; j++)
                    acc[i][j] = fmaf(a[i], b[j], acc[i][j]);
        }
    };

    loadA(0); loadB(0);
    store(0);
    __syncthreads();
    int buf = 0;
    for (int k0 = 0; k0 < K; k0 += BK) {
        bool has_next = (k0 + BK) < K;
        if (has_next) { loadA(k0 + BK); loadB(k0 + BK); }
        compute(buf);
        if (has_next) {
            store(buf ^ 1);
            __syncthreads();
            buf ^= 1;
        }
    }

    #pragma unroll
    for (int i = 0; i < TM; i++) {
        int gm = m0 + ty * TM + i;
        if (gm >= M) continue;
        int w   = gm % W;
        int tmp = gm / W;
        int h   = tmp % Hout;
        int b   = tmp / Hout;
        #pragma unroll
        for (int j = 0; j < TN; j++) {
            int gn = n0 + tx * TN + j;
            if (gn >= O) continue;
            size_t idx = (((size_t)b * O + gn) * Hout + h) * W + w;
            float v = acc[i][j] + bias[gn];
            if (ACC) out[idx] = out[idx] + v;
            else     out[idx] = v;
        }
    }
}

// ===================== host-side dispatch =====================
static void run_lin_tc(const float* A, const float* W, const float* b,
                       float* out, int M, int N, int K, bool relu)
{
    int c32 = ((N + 31) / 32) * 32;
    int c64 = ((N + 63) / 64) * 64;
    if (c32 < c64) {
        dim3 g((M + 127) / 128, (N + 31) / 32);
        if (relu) tc_lin<32, true ><<<g, 256>>>(A, W, b, out, M, N, K);
        else      tc_lin<32, false><<<g, 256>>>(A, W, b, out, M, N, K);
    } else {
        dim3 g((M + 127) / 128, (N + 63) / 64);
        if (relu) tc_lin<64, true ><<<g, 256>>>(A, W, b, out, M, N, K);
        else      tc_lin<64, false><<<g, 256>>>(A, W, b, out, M, N, K);
    }
}

template<int KH, bool ACC>
static void run_conv_simt(const float* In, const float* W, const float* b,
                          float* out, int B, int I, int Hin, int Wd, int O, int pad)
{
    int Hout = Hin + 2 * pad - KH + 1;
    int M = B * Hout * Wd;
    int c32 = ((O + 31) / 32) * 32;
    int c64 = ((O + 63) / 64) * 64;
    if (c32 < c64) {
        dim3 g((M + 255) / 256, (O + 31) / 32);
        conv_kernel<256, 32, KH, ACC><<<g, 256>>>(In, W, b, out, B, I, Hin, Wd, O, pad);
    } else {
        dim3 g((M + 127) / 128, (O + 63) / 64);
        conv_kernel<128, 64, KH, ACC><<<g, 256>>>(In, W, b, out, B, I, Hin, Wd, O, pad);
    }
}

template<int KH, bool ACC>
static void run_conv_tc(const float* In, const float* W, const float* b,
                        float* out, int B, int I, int Hin, int Wd, int O, int pad)
{
    int Hout = Hin + 2 * pad - KH + 1;
    int M = B * Hout * Wd;
    int K = I * KH;
    dim3 g((M + 127) / 128, (O + 63) / 64);
    if ((K & 1) == 0)
        tc_conv<KH, ACC, true ><<<g, 256>>>(In, W, b, out, B, I, Hin, Wd, O, pad);
    else
        tc_conv<KH, ACC, false><<<g, 256>>>(In, W, b, out, B, I, Hin, Wd, O, pad);
}

extern "C" void kernel_launch(void* const* d_in, const int* in_sizes, int n_in,
                              void* d_out, int out_size)
{
    const float* x   = (const float*)d_in[0];
    const float* W0a = (const float*)d_in[1];  const float* b0a = (const float*)d_in[2];
    const float* Wl0 = (const float*)d_in[3];  const float* bl0 = (const float*)d_in[4];
    const float* W0b = (const float*)d_in[5];  const float* b0b = (const float*)d_in[6];
    const float* Wr0 = (const float*)d_in[7];  const float* br0 = (const float*)d_in[8];
    const float* W0c = (const float*)d_in[9];  const float* b0c = (const float*)d_in[10];
    const float* W1  = (const float*)d_in[11]; const float* b1  = (const float*)d_in[12];
    const float* Wl1 = (const float*)d_in[13]; const float* bl1 = (const float*)d_in[14];
    const float* W2  = (const float*)d_in[15]; const float* b2  = (const float*)d_in[16];
    const float* Wra = (const float*)d_in[17]; const float* bra = (const float*)d_in[18];
    const float* Wa  = (const float*)d_in[19]; const float* ba  = (const float*)d_in[20];
    const float* W3  = (const float*)d_in[21]; const float* b3  = (const float*)d_in[22];
    const float* Wl2 = (const float*)d_in[23]; const float* bl2 = (const float*)d_in[24];
    const float* W4  = (const float*)d_in[25]; const float* b4  = (const float*)d_in[26];
    const float* Wrb = (const float*)d_in[27]; const float* brb = (const float*)d_in[28];
    const float* Wb  = (const float*)d_in[29]; const float* bb  = (const float*)d_in[30];

    float* out = (float*)d_out;

    float *S1, *S2, *S3;
    cudaGetSymbolAddress((void**)&S1, g_s1);
    cudaGetSymbolAddress((void**)&S2, g_s2);
    cudaGetSymbolAddress((void**)&S3, g_s3);

    const int B = 1024;

    // ---------------- block 0 ----------------
    run_conv_simt<3, false>(x,  W0a, b0a, S1, B, 1, 5, 127, 5, 1);   // SIMT
    run_lin_tc(S1, Wl0, bl0, S2, B * 5 * 5, 81, 127, true);          // TC lin
    run_conv_simt<3, false>(S2, W0b, b0b, S3, B, 5, 5, 81, 25, 1);   // SIMT
    run_lin_tc(x,  Wr0, br0, S1, B * 1 * 5, 81, 127, false);         // TC lin
    run_conv_simt<1, true >(S1, W0c, b0c, S3, B, 1, 5, 81, 25, 0);   // SIMT

    // ---------------- block 1 ----------------
    run_conv_tc  <3, false>(S3, W1, b1, S1, B, 25, 5, 81, 75, 1);    // TC conv (K=75 odd)
    run_lin_tc(S1, Wl1, bl1, S2, B * 75 * 5, 41, 81, true);          // TC lin
    run_conv_tc  <3, false>(S2, W2, b2, S1, B, 75, 5, 41, 150, 1);   // TC conv (K=225 odd)
    run_lin_tc(S3, Wra, bra, S2, B * 25 * 5, 41, 81, false);         // TC lin
    run_conv_tc  <1, true >(S2, Wa, ba, S1, B, 25, 5, 41, 150, 0);   // TC conv (K=25 odd)

    // ---------------- block 2 ----------------
    run_conv_tc  <2, false>(S1, W3, b3, S3, B, 150, 5, 41, 300, 0);  // TC conv (K=300 even, vec)
    run_lin_tc(S3, Wl2, bl2, S2, B * 300 * 4, 18, 41, true);         // TC lin
    run_conv_tc  <2, false>(S2, W4, b4, out, B, 300, 4, 18, 512, 0); // TC conv (K=600 even, vec)
    run_lin_tc(S1, Wrb, brb, S3, B * 150 * 5, 18, 41, false);        // TC lin
    run_conv_tc  <3, true >(S3, Wb, bb, out, B, 150, 5, 18, 512, 0); // TC conv (K=450 even, vec)
}